// round 10
// baseline (speedup 1.0000x reference)
#include <cuda_runtime.h>

// DropBlock, single fused launch, persistent one-wave grid,
// contiguous per-CTA chunks, 4x unrolled streaming multiply.
// x [64,256,64,64] f32, u [58,58] f32. BLOCK_SIZE=7, DROP_PROB=0.1.

#define H 64
#define W 64
#define HW 4096
#define US 58           // H - BS + 1
#define BS 7
#define DROP_PROB 0.1f
#define THREADS 256

typedef unsigned long long u64;

__global__ __launch_bounds__(THREADS, 8)   // force regs<=32: 8 CTAs/SM
void dropblock_fused_kernel(const float* __restrict__ u,
                            const float4* __restrict__ x4,
                            float4* __restrict__ out4,
                            int n4) {
    __shared__ u64 s_hdil[US];
    __shared__ u64 s_vdil[H];
    __shared__ int s_sum;
    __shared__ __align__(16) float s_mult[HW];   // 16 KB

    int tid  = threadIdx.x;        // 256 threads = 8 warps
    int lane = tid & 31;
    int warp = tid >> 5;
    if (tid == 0) s_sum = 0;

    // ---- Phase 1: mask via ballots (front-batched u loads, MLP~16/thread) ----
    float va[8], vb[8];
    #pragma unroll
    for (int k = 0; k < 8; k++) {
        int row = warp + k * 8;
        if (row < US) {
            const float* r = u + row * US;
            va[k] = __ldg(&r[lane]);
            vb[k] = (lane + 32 < US) ? __ldg(&r[lane + 32]) : 1.0f;
        } else {
            va[k] = 1.0f; vb[k] = 1.0f;
        }
    }
    #pragma unroll
    for (int k = 0; k < 8; k++) {
        int row = warp + k * 8;
        unsigned m0 = __ballot_sync(0xFFFFFFFFu, va[k] < DROP_PROB);
        unsigned m1 = __ballot_sync(0xFFFFFFFFu, vb[k] < DROP_PROB);
        if (row < US && lane == 0) {
            u64 b = (u64)m0 | ((u64)m1 << 32);
            u64 h = b;
            #pragma unroll
            for (int s = 1; s < BS; s++) h |= b << s;   // horizontal dilation
            s_hdil[row] = h;
        }
    }
    __syncthreads();

    if (tid < H) {
        int i0 = tid - (BS - 1); if (i0 < 0) i0 = 0;
        int i1 = tid;            if (i1 > US - 1) i1 = US - 1;
        u64 v = 0ULL;
        for (int i = i0; i <= i1; i++) v |= s_hdil[i];
        s_vdil[tid] = v;
        int keep = W - __popcll(v);
        #pragma unroll
        for (int off = 16; off > 0; off >>= 1)
            keep += __shfl_down_sync(0xFFFFFFFFu, keep, off);
        if (lane == 0) atomicAdd(&s_sum, keep);
    }
    __syncthreads();

    float scale = (float)HW / (float)s_sum;

    float4* mt4 = reinterpret_cast<float4*>(s_mult);
    #pragma unroll
    for (int k = 0; k < 4; k++) {
        int q = tid + k * 256;
        int y = q >> 4;
        int x = (q & 15) * 4;
        u64 v = s_vdil[y];
        float4 f;
        f.x = ((v >> (x + 0)) & 1ULL) ? 0.0f : scale;
        f.y = ((v >> (x + 1)) & 1ULL) ? 0.0f : scale;
        f.z = ((v >> (x + 2)) & 1ULL) ? 0.0f : scale;
        f.w = ((v >> (x + 3)) & 1ULL) ? 0.0f : scale;
        mt4[q] = f;
    }
    __syncthreads();

    // ---- Phase 2: contiguous chunk per CTA, 4x unrolled (MLP=4/thread) ----
    int nblocks = gridDim.x;
    int chunk = (n4 + nblocks - 1) / nblocks;       // float4s per CTA
    int start = blockIdx.x * chunk;
    int end   = start + chunk; if (end > n4) end = n4;

    int i = start + tid;
    // main: 4 independent float4s per thread per iteration
    for (; i + 3 * THREADS < end; i += 4 * THREADS) {
        float4 v0 = x4[i];
        float4 v1 = x4[i + THREADS];
        float4 v2 = x4[i + 2 * THREADS];
        float4 v3 = x4[i + 3 * THREADS];
        float4 m0 = mt4[(i)               & 1023];
        float4 m1 = mt4[(i + THREADS)     & 1023];
        float4 m2 = mt4[(i + 2 * THREADS) & 1023];
        float4 m3 = mt4[(i + 3 * THREADS) & 1023];
        v0.x *= m0.x; v0.y *= m0.y; v0.z *= m0.z; v0.w *= m0.w;
        v1.x *= m1.x; v1.y *= m1.y; v1.z *= m1.z; v1.w *= m1.w;
        v2.x *= m2.x; v2.y *= m2.y; v2.z *= m2.z; v2.w *= m2.w;
        v3.x *= m3.x; v3.y *= m3.y; v3.z *= m3.z; v3.w *= m3.w;
        out4[i]               = v0;
        out4[i + THREADS]     = v1;
        out4[i + 2 * THREADS] = v2;
        out4[i + 3 * THREADS] = v3;
    }
    for (; i < end; i += THREADS) {
        float4 v = x4[i];
        float4 m = mt4[i & 1023];
        v.x *= m.x; v.y *= m.y; v.z *= m.z; v.w *= m.w;
        out4[i] = v;
    }
}

extern "C" void kernel_launch(void* const* d_in, const int* in_sizes, int n_in,
                              void* d_out, int out_size) {
    const float* x = (const float*)d_in[0];
    const float* u = (const float*)d_in[1];
    float* out = (float*)d_out;

    // One-wave grid sized from real occupancy (host-side, capture-safe).
    int dev = 0;
    cudaGetDevice(&dev);
    int sms = 148;
    cudaDeviceGetAttribute(&sms, cudaDevAttrMultiProcessorCount, dev);
    int nb = 8;
    cudaOccupancyMaxActiveBlocksPerMultiprocessor(
        &nb, dropblock_fused_kernel, THREADS, 0);
    if (nb < 1) nb = 1;
    int blocks = sms * nb;

    int n4 = out_size / 4;   // 16,777,216 float4s
    dropblock_fused_kernel<<<blocks, THREADS>>>(
        u, (const float4*)x, (float4*)out, n4);
}

// round 11
// speedup vs baseline: 1.3214x; 1.3214x over previous
#include <cuda_runtime.h>

// DropBlock: x [64,256,64,64] f32, u [58,58] f32. BLOCK_SIZE=7, DROP_PROB=0.1
// Best structure (R8): k1 (1024-thr ballot bitboards, all u loads parallel)
//   --PDL--> k2 (flat-grid streaming multiply, plain ld/st, 6.27 TB/s).
// k2 front-loads x (mask-independent), then cudaGridDependencySynchronize().
// n4 = 2^24 divides evenly by 256 -> exact grid, no bounds check.

#define H 64
#define W 64
#define HW 4096
#define US 58           // H - BS + 1
#define BS 7
#define DROP_PROB 0.1f
#define K2_THREADS 256

typedef unsigned long long u64;

__device__ __align__(16) float d_mult[HW];

// ---------------- Kernel 1: mask via warp ballots, max MLP ----------------
// 1024 threads = 32 warps; warp w owns rows w and w+32. All u loads issue
// before any ballot -> one DRAM round-trip.
__global__ __launch_bounds__(1024)
void build_mask_kernel(const float* __restrict__ u) {
    cudaTriggerProgrammaticLaunchCompletion();

    __shared__ u64 s_hdil[US];
    __shared__ u64 s_vdil[H];
    __shared__ int s_sum;

    int tid  = threadIdx.x;
    int lane = tid & 31;
    int warp = tid >> 5;
    if (tid == 0) s_sum = 0;

    int rowA = warp;          // always < 58
    int rowB = warp + 32;     // valid if < 58
    const float* rA = u + rowA * US;

    float a0 = rA[lane];
    float a1 = (lane + 32 < US) ? rA[lane + 32] : 1.0f;
    float b0 = 1.0f, b1 = 1.0f;
    if (rowB < US) {
        const float* rB = u + rowB * US;
        b0 = rB[lane];
        b1 = (lane + 32 < US) ? rB[lane + 32] : 1.0f;
    }

    {
        unsigned m0 = __ballot_sync(0xFFFFFFFFu, a0 < DROP_PROB);
        unsigned m1 = __ballot_sync(0xFFFFFFFFu, a1 < DROP_PROB);
        u64 b = (u64)m0 | ((u64)m1 << 32);
        u64 h = b;
        #pragma unroll
        for (int s = 1; s < BS; s++) h |= b << s;
        if (lane == 0) s_hdil[rowA] = h;
    }
    {
        unsigned m0 = __ballot_sync(0xFFFFFFFFu, b0 < DROP_PROB);
        unsigned m1 = __ballot_sync(0xFFFFFFFFu, b1 < DROP_PROB);
        if (rowB < US && lane == 0) {
            u64 b = (u64)m0 | ((u64)m1 << 32);
            u64 h = b;
            #pragma unroll
            for (int s = 1; s < BS; s++) h |= b << s;
            s_hdil[rowB] = h;
        }
    }
    __syncthreads();

    // Vertical dilation + keep count (threads 0..63)
    if (tid < H) {
        int i0 = tid - (BS - 1); if (i0 < 0) i0 = 0;
        int i1 = tid;            if (i1 > US - 1) i1 = US - 1;
        u64 v = 0ULL;
        for (int i = i0; i <= i1; i++) v |= s_hdil[i];
        s_vdil[tid] = v;
        int keep = W - __popcll(v);
        #pragma unroll
        for (int off = 16; off > 0; off >>= 1)
            keep += __shfl_down_sync(0xFFFFFFFFu, keep, off);
        if (lane == 0) atomicAdd(&s_sum, keep);
    }
    __syncthreads();

    float scale = (float)HW / (float)s_sum;

    // One float4 per thread (1024 float4s = 4096 floats).
    int q = tid;
    int y = q >> 4;
    int x = (q & 15) * 4;
    u64 v = s_vdil[y];
    float4 f;
    f.x = ((v >> (x + 0)) & 1ULL) ? 0.0f : scale;
    f.y = ((v >> (x + 1)) & 1ULL) ? 0.0f : scale;
    f.z = ((v >> (x + 2)) & 1ULL) ? 0.0f : scale;
    f.w = ((v >> (x + 3)) & 1ULL) ? 0.0f : scale;
    reinterpret_cast<float4*>(d_mult)[q] = f;
}

// ---------------- Kernel 2: streaming multiply (PDL consumer) ----------------
// Exact grid (no bounds check): caller guarantees n4 % K2_THREADS == 0
// on this problem (n4 = 2^24). Plain loads/stores: best measured 6271 GB/s.
__global__ __launch_bounds__(K2_THREADS)
void apply_mask_kernel(const float4* __restrict__ x4,
                       float4* __restrict__ out4) {
    int idx = blockIdx.x * K2_THREADS + threadIdx.x;

    float4 v = x4[idx];              // mask-independent: overlaps k1

    cudaGridDependencySynchronize(); // d_mult now visible

    const float4* m4 = reinterpret_cast<const float4*>(d_mult);
    float4 m = __ldg(&m4[idx & 1023]);
    v.x *= m.x; v.y *= m.y; v.z *= m.z; v.w *= m.w;
    out4[idx] = v;
}

// Fallback with bounds check in case out_size isn't divisible.
__global__ __launch_bounds__(K2_THREADS)
void apply_mask_kernel_guard(const float4* __restrict__ x4,
                             float4* __restrict__ out4, int n4) {
    int idx = blockIdx.x * K2_THREADS + threadIdx.x;
    bool valid = idx < n4;
    float4 v;
    if (valid) v = x4[idx];
    cudaGridDependencySynchronize();
    if (!valid) return;
    const float4* m4 = reinterpret_cast<const float4*>(d_mult);
    float4 m = __ldg(&m4[idx & 1023]);
    v.x *= m.x; v.y *= m.y; v.z *= m.z; v.w *= m.w;
    out4[idx] = v;
}

extern "C" void kernel_launch(void* const* d_in, const int* in_sizes, int n_in,
                              void* d_out, int out_size) {
    const float* x = (const float*)d_in[0];
    const float* u = (const float*)d_in[1];
    float* out = (float*)d_out;

    build_mask_kernel<<<1, 1024>>>(u);

    int n4 = out_size / 4;               // 16,777,216 float4s (2^24)

    cudaLaunchConfig_t cfg = {};
    cfg.blockDim = dim3(K2_THREADS, 1, 1);
    cfg.dynamicSmemBytes = 0;
    cfg.stream = 0;
    cudaLaunchAttribute attr[1];
    attr[0].id = cudaLaunchAttributeProgrammaticStreamSerialization;
    attr[0].val.programmaticStreamSerializationAllowed = 1;
    cfg.attrs = attr;
    cfg.numAttrs = 1;

    if ((n4 % K2_THREADS) == 0) {
        cfg.gridDim = dim3(n4 / K2_THREADS, 1, 1);
        cudaLaunchKernelEx(&cfg, apply_mask_kernel,
                           (const float4*)x, (float4*)out);
    } else {
        cfg.gridDim = dim3((n4 + K2_THREADS - 1) / K2_THREADS, 1, 1);
        cudaLaunchKernelEx(&cfg, apply_mask_kernel_guard,
                           (const float4*)x, (float4*)out, n4);
    }
}

// round 12
// speedup vs baseline: 1.6139x; 1.2214x over previous
#include <cuda_runtime.h>

// DropBlock: x [64,256,64,64] f32, u [58,58] f32. BLOCK_SIZE=7, DROP_PROB=0.1
//
// KEY INSIGHT: with p=0.1 over 58x58 positions, P(pixel kept) = 0.9^49 ~ 0.6%.
// The multiplier table is ~99.4% zeros -> for those pixels out = 0 exactly and
// x need not be read. k2 tests the (L1-resident, 16KB) multiplier first and
// loads x only where the mask is nonzero: DRAM traffic drops from 536MB
// (268 read + 268 write) to ~270MB (268 write + ~2MB read).
//
// k1 (ballot bitboards) --PDL--> k2 (mask-gated streaming store).

#define H 64
#define W 64
#define HW 4096
#define US 58           // H - BS + 1
#define BS 7
#define DROP_PROB 0.1f
#define K2_THREADS 256

typedef unsigned long long u64;

__device__ __align__(16) float d_mult[HW];

// ---------------- Kernel 1: mask via warp ballots, max MLP ----------------
__global__ __launch_bounds__(1024)
void build_mask_kernel(const float* __restrict__ u) {
    cudaTriggerProgrammaticLaunchCompletion();

    __shared__ u64 s_hdil[US];
    __shared__ u64 s_vdil[H];
    __shared__ int s_sum;

    int tid  = threadIdx.x;
    int lane = tid & 31;
    int warp = tid >> 5;
    if (tid == 0) s_sum = 0;

    int rowA = warp;          // always < 58
    int rowB = warp + 32;     // valid if < 58
    const float* rA = u + rowA * US;

    float a0 = rA[lane];
    float a1 = (lane + 32 < US) ? rA[lane + 32] : 1.0f;
    float b0 = 1.0f, b1 = 1.0f;
    if (rowB < US) {
        const float* rB = u + rowB * US;
        b0 = rB[lane];
        b1 = (lane + 32 < US) ? rB[lane + 32] : 1.0f;
    }

    {
        unsigned m0 = __ballot_sync(0xFFFFFFFFu, a0 < DROP_PROB);
        unsigned m1 = __ballot_sync(0xFFFFFFFFu, a1 < DROP_PROB);
        u64 b = (u64)m0 | ((u64)m1 << 32);
        u64 h = b;
        #pragma unroll
        for (int s = 1; s < BS; s++) h |= b << s;
        if (lane == 0) s_hdil[rowA] = h;
    }
    {
        unsigned m0 = __ballot_sync(0xFFFFFFFFu, b0 < DROP_PROB);
        unsigned m1 = __ballot_sync(0xFFFFFFFFu, b1 < DROP_PROB);
        if (rowB < US && lane == 0) {
            u64 b = (u64)m0 | ((u64)m1 << 32);
            u64 h = b;
            #pragma unroll
            for (int s = 1; s < BS; s++) h |= b << s;
            s_hdil[rowB] = h;
        }
    }
    __syncthreads();

    if (tid < H) {
        int i0 = tid - (BS - 1); if (i0 < 0) i0 = 0;
        int i1 = tid;            if (i1 > US - 1) i1 = US - 1;
        u64 v = 0ULL;
        for (int i = i0; i <= i1; i++) v |= s_hdil[i];
        s_vdil[tid] = v;
        int keep = W - __popcll(v);
        #pragma unroll
        for (int off = 16; off > 0; off >>= 1)
            keep += __shfl_down_sync(0xFFFFFFFFu, keep, off);
        if (lane == 0) atomicAdd(&s_sum, keep);
    }
    __syncthreads();

    float scale = (float)HW / (float)s_sum;

    int q = tid;                 // one float4 per thread
    int y = q >> 4;
    int x = (q & 15) * 4;
    u64 v = s_vdil[y];
    float4 f;
    f.x = ((v >> (x + 0)) & 1ULL) ? 0.0f : scale;
    f.y = ((v >> (x + 1)) & 1ULL) ? 0.0f : scale;
    f.z = ((v >> (x + 2)) & 1ULL) ? 0.0f : scale;
    f.w = ((v >> (x + 3)) & 1ULL) ? 0.0f : scale;
    reinterpret_cast<float4*>(d_mult)[q] = f;
}

// ---------------- Kernel 2: mask-gated streaming store (PDL consumer) ----
// Read the 16KB multiplier table (L1-hot) first; load x only where nonzero.
__global__ __launch_bounds__(K2_THREADS)
void apply_mask_kernel(const float4* __restrict__ x4,
                       float4* __restrict__ out4) {
    int idx = blockIdx.x * K2_THREADS + threadIdx.x;

    cudaGridDependencySynchronize();   // d_mult visible

    const float4* m4 = reinterpret_cast<const float4*>(d_mult);
    float4 m = __ldg(&m4[idx & 1023]);

    float4 r = make_float4(0.0f, 0.0f, 0.0f, 0.0f);
    if ((m.x != 0.0f) | (m.y != 0.0f) | (m.z != 0.0f) | (m.w != 0.0f)) {
        float4 v = x4[idx];
        r.x = v.x * m.x; r.y = v.y * m.y; r.z = v.z * m.z; r.w = v.w * m.w;
    }
    out4[idx] = r;
}

// Guarded fallback if out_size isn't divisible by 4*K2_THREADS.
__global__ __launch_bounds__(K2_THREADS)
void apply_mask_kernel_guard(const float4* __restrict__ x4,
                             float4* __restrict__ out4, int n4) {
    int idx = blockIdx.x * K2_THREADS + threadIdx.x;
    cudaGridDependencySynchronize();
    if (idx >= n4) return;
    const float4* m4 = reinterpret_cast<const float4*>(d_mult);
    float4 m = __ldg(&m4[idx & 1023]);
    float4 r = make_float4(0.0f, 0.0f, 0.0f, 0.0f);
    if ((m.x != 0.0f) | (m.y != 0.0f) | (m.z != 0.0f) | (m.w != 0.0f)) {
        float4 v = x4[idx];
        r.x = v.x * m.x; r.y = v.y * m.y; r.z = v.z * m.z; r.w = v.w * m.w;
    }
    out4[idx] = r;
}

extern "C" void kernel_launch(void* const* d_in, const int* in_sizes, int n_in,
                              void* d_out, int out_size) {
    const float* x = (const float*)d_in[0];
    const float* u = (const float*)d_in[1];
    float* out = (float*)d_out;

    build_mask_kernel<<<1, 1024>>>(u);

    int n4 = out_size / 4;               // 16,777,216 float4s (2^24)

    cudaLaunchConfig_t cfg = {};
    cfg.blockDim = dim3(K2_THREADS, 1, 1);
    cfg.dynamicSmemBytes = 0;
    cfg.stream = 0;
    cudaLaunchAttribute attr[1];
    attr[0].id = cudaLaunchAttributeProgrammaticStreamSerialization;
    attr[0].val.programmaticStreamSerializationAllowed = 1;
    cfg.attrs = attr;
    cfg.numAttrs = 1;

    if ((n4 % K2_THREADS) == 0) {
        cfg.gridDim = dim3(n4 / K2_THREADS, 1, 1);
        cudaLaunchKernelEx(&cfg, apply_mask_kernel,
                           (const float4*)x, (float4*)out);
    } else {
        cfg.gridDim = dim3((n4 + K2_THREADS - 1) / K2_THREADS, 1, 1);
        cudaLaunchKernelEx(&cfg, apply_mask_kernel_guard,
                           (const float4*)x, (float4*)out, n4);
    }
}